// round 14
// baseline (speedup 1.0000x reference)
#include <cuda_runtime.h>
#include <cuda_bf16.h>
#include <math.h>

// Problem constants (fixed shapes)
#define BB 4
#define NN 20000
#define EE 640000
#define FF 64
#define ED 16
#define C1 128   // H1*HID
#define H1 8
#define HID 16

typedef unsigned long long u64;

// ---------------- packed f32x2 helpers ----------------
__device__ __forceinline__ u64 F2PK(float x, float y) {
    u64 r; asm("mov.b64 %0, {%1, %2};" : "=l"(r) : "f"(x), "f"(y)); return r;
}
__device__ __forceinline__ float2 F2UP(u64 v) {
    float2 r; asm("mov.b64 {%0, %1}, %2;" : "=f"(r.x), "=f"(r.y) : "l"(v)); return r;
}
__device__ __forceinline__ u64 FMA2(u64 a, u64 b, u64 c) {
    u64 d; asm("fma.rn.f32x2 %0, %1, %2, %3;" : "=l"(d) : "l"(a), "l"(b), "l"(c)); return d;
}
__device__ __forceinline__ u64 ADD2(u64 a, u64 b) {
    u64 d; asm("add.rn.f32x2 %0, %1, %2;" : "=l"(d) : "l"(a), "l"(b)); return d;
}
__device__ __forceinline__ u64 MUL2(u64 a, u64 b) {
    u64 d; asm("mul.rn.f32x2 %0, %1, %2;" : "=l"(d) : "l"(a), "l"(b)); return d;
}
// packed leaky-relu(0.2): lrelu(z) = 0.6*z + 0.4*|z|
__device__ __forceinline__ u64 LRELU2(u64 z) {
    u64 az = z & 0x7FFFFFFF7FFFFFFFull;
    return FMA2(z, 0x3F19999A3F19999Aull, MUL2(az, 0x3ECCCCCD3ECCCCCDull));
}
__device__ __forceinline__ u64 SHFLX64(u64 v, int m) {
    return __shfl_xor_sync(0xffffffffu, v, m);
}

// ---------------- scratch (device globals, allowed) ----------------
__device__ float g_xl1[(size_t)BB*NN*C1];   // conv1 source transform (= skip)
__device__ float g_xr1[(size_t)BB*NN*C1];   // conv1 target transform
__device__ float g_out1[(size_t)BB*NN*C1];  // hx after conv1+elu

// packed (conv2, skip) projections: [node][ch] -> float2 (slot0=conv2, slot1=skip)
__device__ float g_xlP[(size_t)BB*NN*HID*2];
__device__ float g_xrP[(size_t)BB*NN*HID*2];

// CSR sort scratch.
// INVARIANT: g_deg is all-zero on entry to kernel_launch (zero at module load;
// k_build re-zeroes it after consuming it, every call).
__device__ int g_deg[BB*NN];
__device__ int g_off[BB*NN];
__device__ int g_cur[BB*NN];
__device__ int2 g_sedge[(size_t)BB*EE];   // (src, eid) sorted by dst

// ---------------- fused CSR build: count + scan (per-batch block) ----------------
// grid BB, block 1024. Each block handles one batch: counts dst degrees with
// global atomics (visible after __syncthreads, block-scope fence), scans to
// offsets, then restores the g_deg all-zero invariant.
__global__ void k_build(const int* __restrict__ eidx) {
    int b = blockIdx.x, tid = threadIdx.x;
    int lane = tid & 31, wid = tid >> 5;
    const int* dsts = eidx + (size_t)b * 2 * EE + EE;
    // count (this block only touches its own batch's g_deg range)
    for (int e = tid; e < EE; e += 1024)
        atomicAdd(&g_deg[b * NN + dsts[e]], 1);
    __syncthreads();   // block-scope fence: all counts visible
    // exclusive scan over NN degrees
    __shared__ int wsum[32];
    __shared__ int carry;
    if (tid == 0) carry = 0;
    __syncthreads();
    for (int base = 0; base < NN; base += 1024) {
        int i = base + tid;
        int v = (i < NN) ? g_deg[b * NN + i] : 0;
        int x = v;
        #pragma unroll
        for (int d = 1; d < 32; d <<= 1) { int y = __shfl_up_sync(0xffffffffu, x, d); if (lane >= d) x += y; }
        if (lane == 31) wsum[wid] = x;
        __syncthreads();
        if (wid == 0) {
            int w = wsum[lane];
            #pragma unroll
            for (int d = 1; d < 32; d <<= 1) { int y = __shfl_up_sync(0xffffffffu, w, d); if (lane >= d) w += y; }
            wsum[lane] = w;
        }
        __syncthreads();
        int excl = carry + x - v + (wid ? wsum[wid - 1] : 0);
        if (i < NN) { g_off[b * NN + i] = excl; g_cur[b * NN + i] = excl; }
        __syncthreads();
        if (tid == 1023) carry = excl + v;
        __syncthreads();
    }
    // restore the all-zero invariant for the next call
    __syncthreads();
    for (int i = tid; i < NN; i += 1024) g_deg[b * NN + i] = 0;
}

__global__ void k_scatter(const int* __restrict__ eidx) {
    int b = blockIdx.y;
    long e = (long)blockIdx.x * 256 + threadIdx.x;
    if (e >= EE) return;
    int src = eidx[(size_t)b * 2 * EE + e];
    int dst = eidx[(size_t)b * 2 * EE + EE + e];
    int pos = atomicAdd(&g_cur[b * NN + dst], 1);
    g_sedge[(size_t)b * EE + pos] = make_int2(src, (int)e);
}

// ---------------- GEMM1 v2 (register-blocked): xl1 = x@Wl (z=0), xr1 = x@Wr (z=1) ----------------
__global__ void k_gemm1(const float* __restrict__ x,
                        const float* __restrict__ Wl, const float* __restrict__ Wr) {
    __shared__ float sW[FF * C1];    // 32KB
    __shared__ float sx[64][FF];     // 16KB
    const float* W = blockIdx.z ? Wr : Wl;
    float* out = blockIdx.z ? g_xr1 : g_xl1;
    int tid = threadIdx.x, b = blockIdx.y;
    for (int i = tid; i < FF * C1 / 4; i += 256)
        ((float4*)sW)[i] = ((const float4*)W)[i];
    int row0 = blockIdx.x * 64;
    #pragma unroll
    for (int j = 0; j < 4; j++) {
        int idx = tid + j * 256;
        int r4 = idx >> 4, kq = idx & 15;
        int row = row0 + r4;
        float4 v = make_float4(0.f, 0.f, 0.f, 0.f);
        if (row < NN) v = *(const float4*)&x[((size_t)b*NN + row)*FF + kq*4];
        ((float4*)&sx[r4][0])[kq] = v;
    }
    __syncthreads();
    int cp = tid & 31;
    int rg = tid >> 5;
    u64 acc[8][2];
    #pragma unroll
    for (int rr = 0; rr < 8; rr++) { acc[rr][0] = 0; acc[rr][1] = 0; }
    for (int k = 0; k < FF; k++) {
        float4 w = *(const float4*)&sW[k*C1 + cp*4];
        u64 w01 = F2PK(w.x, w.y), w23 = F2PK(w.z, w.w);
        #pragma unroll
        for (int rr = 0; rr < 8; rr++) {
            float xv = sx[rg*8 + rr][k];
            u64 xp = F2PK(xv, xv);
            acc[rr][0] = FMA2(xp, w01, acc[rr][0]);
            acc[rr][1] = FMA2(xp, w23, acc[rr][1]);
        }
    }
    #pragma unroll
    for (int rr = 0; rr < 8; rr++) {
        int row = row0 + rg*8 + rr;
        if (row < NN) {
            float2 p0 = F2UP(acc[rr][0]), p1 = F2UP(acc[rr][1]);
            *(float4*)&out[((size_t)b*NN + row)*C1 + cp*4] = make_float4(p0.x, p0.y, p1.x, p1.y);
        }
    }
}

// ---------------- conv1: warp-per-dst-node, 2-edge interleaved, packed f32x2 ----------------
// (1098us config) lane handles 4 channels = 2 pairs. grid: (ceil(NN/8), BB), block 256
// eattr for the A/B edge pair is loaded by the full warp: lanes 0-15 hold edge A's
// 16 attrs, lanes 16-31 hold edge B's; shfl sources are k and 16|k.
__global__ void k_edge1g(const float* __restrict__ eattr,
                         const float* __restrict__ We, const float* __restrict__ att,
                         const float* __restrict__ b1) {
    __shared__ float sWe[ED * C1];  // 8KB
    __shared__ float satt[H1 * HID];
    int tid = threadIdx.x, b = blockIdx.y;
    for (int i = tid; i < ED * C1; i += 256) sWe[i] = We[i];
    if (tid < H1 * HID) satt[tid] = att[tid];
    __syncthreads();
    int warp = tid >> 5, lane = tid & 31;
    int n = blockIdx.x * 8 + warp;
    if (n >= NN) return;
    int nb = b * NN + n;
    int start = g_off[nb];
    int end = (n == NN - 1) ? EE : g_off[nb + 1];
    int c0 = lane * 4;
    const float4* xl1v = (const float4*)g_xl1;
    size_t rowq = ((size_t)b * NN) * (C1 / 4) + (size_t)lane;
    float4 xrf = ((const float4*)g_xr1)[(size_t)nb * (C1/4) + lane];
    u64 xr0 = F2PK(xrf.x, xrf.y), xr1 = F2PK(xrf.z, xrf.w);
    u64 acc0 = 0, acc1 = 0;
    float den = 0.f;
    int h = lane >> 2;
    int cl = (lane & 3) * 4;
    u64 attp0 = F2PK(satt[h*HID+cl+0], satt[h*HID+cl+1]);
    u64 attp1 = F2PK(satt[h*HID+cl+2], satt[h*HID+cl+3]);
    const int2* sedge = g_sedge + (size_t)b * EE;
    const float* eab = eattr + (size_t)b * EE * ED;
    int halfe = lane >> 4;     // 0 -> edge A, 1 -> edge B (for the eattr load)
    int tl = lane & 15;

    float av = 0.f;
    float4 xlA = make_float4(0,0,0,0), xlB = make_float4(0,0,0,0);
    if (start < end) {
        int2 eA = sedge[start];
        int2 eB = (start + 1 < end) ? sedge[start + 1] : eA;
        int eid = halfe ? eB.y : eA.y;
        av = eab[(size_t)eid*ED + tl];
        xlA = xl1v[rowq + (size_t)eA.x * (C1/4)];
        if (start + 1 < end) xlB = xl1v[rowq + (size_t)eB.x * (C1/4)];
    }
    for (int i = start; i < end; i += 2) {
        // prefetch next pair
        float av2 = 0.f;
        float4 xlA2 = make_float4(0,0,0,0), xlB2 = make_float4(0,0,0,0);
        if (i + 2 < end) {
            int2 eA = sedge[i + 2];
            int2 eB = (i + 3 < end) ? sedge[i + 3] : eA;
            int eid = halfe ? eB.y : eA.y;
            av2 = eab[(size_t)eid*ED + tl];
            xlA2 = xl1v[rowq + (size_t)eA.x * (C1/4)];
            if (i + 3 < end) xlB2 = xl1v[rowq + (size_t)eB.x * (C1/4)];
        }
        bool validB = (i + 1 < end);

        u64 xlA0 = F2PK(xlA.x, xlA.y), xlA1 = F2PK(xlA.z, xlA.w);
        u64 xlB0 = F2PK(xlB.x, xlB.y), xlB1 = F2PK(xlB.z, xlB.w);
        u64 eeA0 = 0, eeA1 = 0, eeB0 = 0, eeB1 = 0;
        #pragma unroll
        for (int k = 0; k < ED; k++) {
            float aA = __shfl_sync(0xffffffffu, av, k);
            float aB = __shfl_sync(0xffffffffu, av, 16 | k);
            float4 w = *(const float4*)&sWe[k*C1 + c0];   // shared by both edges
            u64 w01 = F2PK(w.x, w.y), w23 = F2PK(w.z, w.w);
            u64 aAp = F2PK(aA, aA), aBp = F2PK(aB, aB);
            eeA0 = FMA2(aAp, w01, eeA0);
            eeA1 = FMA2(aAp, w23, eeA1);
            eeB0 = FMA2(aBp, w01, eeB0);
            eeB1 = FMA2(aBp, w23, eeB1);
        }
        u64 gA0 = LRELU2(ADD2(xlA0, ADD2(xr0, eeA0)));
        u64 gA1 = LRELU2(ADD2(xlA1, ADD2(xr1, eeA1)));
        u64 gB0 = LRELU2(ADD2(xlB0, ADD2(xr0, eeB0)));
        u64 gB1 = LRELU2(ADD2(xlB1, ADD2(xr1, eeB1)));
        float2 sfA = F2UP(FMA2(gA1, attp1, MUL2(gA0, attp0)));
        float2 sfB = F2UP(FMA2(gB1, attp1, MUL2(gB0, attp0)));
        float sA = sfA.x + sfA.y;
        float sB = sfB.x + sfB.y;
        sA += __shfl_xor_sync(0xffffffffu, sA, 1);
        sB += __shfl_xor_sync(0xffffffffu, sB, 1);
        sA += __shfl_xor_sync(0xffffffffu, sA, 2);
        sB += __shfl_xor_sync(0xffffffffu, sB, 2);
        float exA = __expf(sA);
        float exB = validB ? __expf(sB) : 0.f;
        u64 exA2 = F2PK(exA, exA), exB2 = F2PK(exB, exB);
        acc0 = FMA2(exA2, xlA0, acc0);
        acc1 = FMA2(exA2, xlA1, acc1);
        acc0 = FMA2(exB2, xlB0, acc0);
        acc1 = FMA2(exB2, xlB1, acc1);
        den += exA + exB;
        av = av2; xlA = xlA2; xlB = xlB2;
    }
    // epilogue: hx = elu(acc/den + bias)
    float inv = 1.f / (den + 1e-16f);
    float4 bv = ((const float4*)b1)[lane];
    float2 a01 = F2UP(acc0), a23 = F2UP(acc1);
    float o0 = a01.x * inv + bv.x;
    float o1 = a01.y * inv + bv.y;
    float o2 = a23.x * inv + bv.z;
    float o3 = a23.y * inv + bv.w;
    o0 = (o0 > 0.f) ? o0 : (__expf(o0) - 1.f);
    o1 = (o1 > 0.f) ? o1 : (__expf(o1) - 1.f);
    o2 = (o2 > 0.f) ? o2 : (__expf(o2) - 1.f);
    o3 = (o3 > 0.f) ? o3 : (__expf(o3) - 1.f);
    ((float4*)g_out1)[(size_t)nb * (C1/4) + lane] = make_float4(o0, o1, o2, o3);
}

// ---------------- GEMM2 v2 (register-blocked): 4 projections -> interleaved (conv2,skip) ----------------
__global__ void k_gemm2(const float* __restrict__ Wl2, const float* __restrict__ Wr2,
                        const float* __restrict__ Wls, const float* __restrict__ Wrs) {
    __shared__ float sW[C1 * 64];    // 32KB
    __shared__ float sh[32][C1];     // 16KB
    __shared__ float ss[32][C1];     // 16KB
    int tid = threadIdx.x, b = blockIdx.y;
    for (int i = tid; i < C1 * HID; i += 256) {
        int k = i >> 4, c = i & 15;
        sW[k*64 + c]      = Wl2[i];
        sW[k*64 + 16 + c] = Wr2[i];
        sW[k*64 + 32 + c] = Wls[i];
        sW[k*64 + 48 + c] = Wrs[i];
    }
    int row0 = blockIdx.x * 32;
    #pragma unroll
    for (int j = 0; j < 4; j++) {
        int idx = tid + j * 256;
        int r4 = idx >> 5, kq = idx & 31;
        int row = row0 + r4;
        float4 hv = make_float4(0.f, 0.f, 0.f, 0.f);
        float4 sk = hv;
        if (row < NN) {
            hv = *(const float4*)&g_out1[((size_t)b*NN + row)*C1 + kq*4];
            sk = *(const float4*)&g_xl1[((size_t)b*NN + row)*C1 + kq*4];
        }
        ((float4*)&sh[r4][0])[kq] = hv;
        ((float4*)&ss[r4][0])[kq] = make_float4(hv.x + sk.x, hv.y + sk.y, hv.z + sk.z, hv.w + sk.w);
    }
    __syncthreads();
    int cp = tid & 31;
    int rg = tid >> 5;
    int arr = cp >> 3;
    const float (*rows)[C1] = (cp < 16) ? sh : ss;
    u64 acc[4] = {0, 0, 0, 0};
    for (int k = 0; k < C1; k++) {
        u64 w = *(const u64*)&sW[k*64 + cp*2];
        #pragma unroll
        for (int rr = 0; rr < 4; rr++) {
            float xv = rows[rg*4 + rr][k];
            acc[rr] = FMA2(F2PK(xv, xv), w, acc[rr]);
        }
    }
    int c = (cp & 7) * 2;
    #pragma unroll
    for (int rr = 0; rr < 4; rr++) {
        int row = row0 + rg*4 + rr;
        if (row < NN) {
            size_t off2 = (((size_t)b*NN + row)*HID + c) * 2;
            float2 res = F2UP(acc[rr]);
            if (arr == 0)      { g_xlP[off2]     = res.x; g_xlP[off2 + 2] = res.y; }
            else if (arr == 1) { g_xrP[off2]     = res.x; g_xrP[off2 + 2] = res.y; }
            else if (arr == 2) { g_xlP[off2 + 1] = res.x; g_xlP[off2 + 3] = res.y; }
            else               { g_xrP[off2 + 1] = res.x; g_xrP[off2 + 3] = res.y; }
        }
    }
}

// ---------------- conv2+skip: warp-per-node, 2 edges/warp, packed (conv2,skip) lanes ----------------
// (1098us config) lanes 0-15: even edges, lanes 16-31: odd edges.
// Warp-uniform trip count; invalid edges contribute exp2 = 0. grid: (ceil(NN/8), BB), block 256
__global__ void k_edge2g(const float* __restrict__ eattr,
                         const float* __restrict__ We2, const float* __restrict__ att2,
                         const float* __restrict__ b2,
                         const float* __restrict__ WeS, const float* __restrict__ attS,
                         const float* __restrict__ bS,
                         const float* __restrict__ linW, const float* __restrict__ linb,
                         const float* __restrict__ lng, const float* __restrict__ lnb,
                         float* __restrict__ out) {
    __shared__ u64 sWeP[ED * HID];   // (We2, WeS) interleaved, 2KB
    __shared__ u64 sattP[HID];
    __shared__ float sLW[HID * HID];
    int tid = threadIdx.x, b = blockIdx.y;
    if (tid < ED*HID) { sWeP[tid] = F2PK(We2[tid], WeS[tid]); sLW[tid] = linW[tid]; }
    if (tid < HID)    sattP[tid] = F2PK(att2[tid], attS[tid]);
    __syncthreads();
    int warp = tid >> 5, lane = tid & 31;
    int n = blockIdx.x * 8 + warp;
    if (n >= NN) return;
    int nb = b * NN + n;
    int start = g_off[nb];
    int end = (n == NN - 1) ? EE : g_off[nb + 1];
    int t = lane & 15;
    int half = lane >> 4;      // 0: even edges, 1: odd edges
    const u64* xlP = (const u64*)g_xlP + (size_t)b * NN * HID;
    u64 xr = ((const u64*)g_xrP)[(size_t)nb * HID + t];
    u64 attp = sattP[t];
    u64 acc = 0, den = 0;
    const int2* sedge = g_sedge + (size_t)b * EE;
    const float* eab = eattr + (size_t)b * EE * ED;

    int cnt = end - start;
    int iters = (cnt + 1) >> 1;          // warp-uniform
    int i = start + half;                // this half's first edge
    bool valid = (i < end);
    float av = 0.f; u64 xl = 0;
    if (valid) {
        int2 e = sedge[i];
        av = eab[(size_t)e.y*ED + t];
        xl = xlP[(size_t)e.x * HID + t];
    }
    for (int it = 0; it < iters; it++) {
        int inext = i + 2;
        bool valid2 = (inext < end);
        float av2 = 0.f; u64 xl2 = 0;
        if (valid2) {
            int2 e = sedge[inext];
            av2 = eab[(size_t)e.y*ED + t];
            xl2 = xlP[(size_t)e.x * HID + t];
        }
        u64 ee = 0;
        #pragma unroll
        for (int k = 0; k < ED; k++) {
            float a = __shfl_sync(0xffffffffu, av, (lane & 16) | k);
            ee = FMA2(F2PK(a, a), sWeP[k*HID + t], ee);
        }
        u64 g = LRELU2(ADD2(xl, ADD2(xr, ee)));
        u64 sp = MUL2(g, attp);
        #pragma unroll
        for (int d = 1; d < 16; d <<= 1) sp = ADD2(sp, SHFLX64(sp, d));
        float2 sf = F2UP(sp);          // (s_conv2, s_skip) for this half's edge
        u64 exp2 = 0;                  // packed (0.0f, 0.0f)
        if (valid) exp2 = F2PK(__expf(sf.x), __expf(sf.y));
        acc = FMA2(exp2, xl, acc);
        den = ADD2(den, exp2);
        i = inext; av = av2; xl = xl2; valid = valid2;
    }
    // combine halves (even/odd edge streams) — all lanes converged here
    acc = ADD2(acc, SHFLX64(acc, 16));
    den = ADD2(den, SHFLX64(den, 16));
    // epilogue: normalize + bias, lin on skip, add, layernorm
    float2 a = F2UP(acc), d2 = F2UP(den);
    float x1 = a.x / (d2.x + 1e-16f) + b2[t];
    float xs = a.y / (d2.y + 1e-16f) + bS[t];
    float x2 = linb[t];
    #pragma unroll
    for (int j = 0; j < HID; j++) {
        float xj = __shfl_sync(0xffffffffu, xs, j);   // lane j holds xs[j] (both halves identical)
        x2 += xj * sLW[t*HID + j];
    }
    float y = x1 + x2;
    float mu = y;
    #pragma unroll
    for (int d = 1; d < 16; d <<= 1) mu += __shfl_xor_sync(0xffffffffu, mu, d);
    mu *= (1.f / 16.f);
    float dv = y - mu;
    float var = dv * dv;
    #pragma unroll
    for (int d = 1; d < 16; d <<= 1) var += __shfl_xor_sync(0xffffffffu, var, d);
    var *= (1.f / 16.f);
    if (lane < 16)
        out[(size_t)nb * HID + t] = dv * rsqrtf(var + 1e-5f) * lng[t] + lnb[t];
}

extern "C" void kernel_launch(void* const* d_in, const int* in_sizes, int n_in,
                              void* d_out, int out_size) {
    const float* x      = (const float*)d_in[0];
    const float* eattr  = (const float*)d_in[1];
    const int*   eidx   = (const int*)  d_in[2];
    const float* c1_Wl  = (const float*)d_in[3];
    const float* c1_Wr  = (const float*)d_in[4];
    const float* c1_We  = (const float*)d_in[5];
    const float* c1_att = (const float*)d_in[6];
    const float* c1_b   = (const float*)d_in[7];
    const float* c2_Wl  = (const float*)d_in[8];
    const float* c2_Wr  = (const float*)d_in[9];
    const float* c2_We  = (const float*)d_in[10];
    const float* c2_att = (const float*)d_in[11];
    const float* c2_b   = (const float*)d_in[12];
    const float* s_Wl   = (const float*)d_in[13];
    const float* s_Wr   = (const float*)d_in[14];
    const float* s_We   = (const float*)d_in[15];
    const float* s_att  = (const float*)d_in[16];
    const float* s_b    = (const float*)d_in[17];
    const float* lin_W  = (const float*)d_in[18];
    const float* lin_b  = (const float*)d_in[19];
    const float* ln_g   = (const float*)d_in[20];
    const float* ln_b   = (const float*)d_in[21];

    // g_deg is all-zero here (module-load init on first call; k_build restores it)
    k_build<<<BB, 1024>>>(eidx);
    k_scatter<<<dim3((EE + 255) / 256, BB), 256>>>(eidx);
    k_gemm1<<<dim3((NN + 63) / 64, BB, 2), 256>>>(x, c1_Wl, c1_Wr);
    k_edge1g<<<dim3((NN + 7) / 8, BB), 256>>>(eattr, c1_We, c1_att, c1_b);   // 4th launch -> profiled
    k_gemm2<<<dim3((NN + 31) / 32, BB), 256>>>(c2_Wl, c2_Wr, s_Wl, s_Wr);
    k_edge2g<<<dim3((NN + 7) / 8, BB), 256>>>(eattr, c2_We, c2_att, c2_b,
                                              s_We, s_att, s_b,
                                              lin_W, lin_b, ln_g, ln_b, (float*)d_out);
}

// round 17
// speedup vs baseline: 1.3372x; 1.3372x over previous
#include <cuda_runtime.h>
#include <cuda_bf16.h>
#include <math.h>

// Problem constants (fixed shapes)
#define BB 4
#define NN 20000
#define EE 640000
#define FF 64
#define ED 16
#define C1 128   // H1*HID
#define H1 8
#define HID 16

typedef unsigned long long u64;

// ---------------- packed f32x2 helpers ----------------
__device__ __forceinline__ u64 F2PK(float x, float y) {
    u64 r; asm("mov.b64 %0, {%1, %2};" : "=l"(r) : "f"(x), "f"(y)); return r;
}
__device__ __forceinline__ float2 F2UP(u64 v) {
    float2 r; asm("mov.b64 {%0, %1}, %2;" : "=f"(r.x), "=f"(r.y) : "l"(v)); return r;
}
__device__ __forceinline__ u64 FMA2(u64 a, u64 b, u64 c) {
    u64 d; asm("fma.rn.f32x2 %0, %1, %2, %3;" : "=l"(d) : "l"(a), "l"(b), "l"(c)); return d;
}
__device__ __forceinline__ u64 ADD2(u64 a, u64 b) {
    u64 d; asm("add.rn.f32x2 %0, %1, %2;" : "=l"(d) : "l"(a), "l"(b)); return d;
}
__device__ __forceinline__ u64 MUL2(u64 a, u64 b) {
    u64 d; asm("mul.rn.f32x2 %0, %1, %2;" : "=l"(d) : "l"(a), "l"(b)); return d;
}
// packed leaky-relu(0.2): lrelu(z) = 0.6*z + 0.4*|z|
__device__ __forceinline__ u64 LRELU2(u64 z) {
    u64 az = z & 0x7FFFFFFF7FFFFFFFull;
    return FMA2(z, 0x3F19999A3F19999Aull, MUL2(az, 0x3ECCCCCD3ECCCCCDull));
}
__device__ __forceinline__ u64 SHFLX64(u64 v, int m) {
    return __shfl_xor_sync(0xffffffffu, v, m);
}

// ---------------- scratch (device globals, allowed) ----------------
__device__ float g_xl1[(size_t)BB*NN*C1];   // conv1 source transform (= skip)
__device__ float g_xr1[(size_t)BB*NN*C1];   // conv1 target transform
__device__ float g_out1[(size_t)BB*NN*C1];  // hx after conv1+elu

// packed (conv2, skip) projections: [node][ch] -> float2 (slot0=conv2, slot1=skip)
__device__ float g_xlP[(size_t)BB*NN*HID*2];
__device__ float g_xrP[(size_t)BB*NN*HID*2];

// CSR sort scratch.
// INVARIANT: g_deg is all-zero on entry to kernel_launch (zero at module load;
// k_scan re-zeroes it after consuming it, every call).
__device__ int g_deg[BB*NN];
__device__ int g_off[BB*NN];
__device__ int g_cur[BB*NN];
__device__ int2 g_sedge[(size_t)BB*EE];   // (src, eid) sorted by dst

// ---------------- CSR build ----------------
__global__ void k_count(const int* __restrict__ eidx) {
    int b = blockIdx.y;
    long e = (long)blockIdx.x * 256 + threadIdx.x;
    if (e >= EE) return;
    int dst = eidx[(size_t)b * 2 * EE + EE + e];
    atomicAdd(&g_deg[b * NN + dst], 1);
}

// per-batch exclusive scan over NN degrees; re-zeroes g_deg afterwards.
// grid BB, block 1024.
__global__ void k_scan() {
    int b = blockIdx.x, tid = threadIdx.x;
    int lane = tid & 31, wid = tid >> 5;
    __shared__ int wsum[32];
    __shared__ int carry;
    if (tid == 0) carry = 0;
    __syncthreads();
    for (int base = 0; base < NN; base += 1024) {
        int i = base + tid;
        int v = (i < NN) ? g_deg[b * NN + i] : 0;
        int x = v;
        #pragma unroll
        for (int d = 1; d < 32; d <<= 1) { int y = __shfl_up_sync(0xffffffffu, x, d); if (lane >= d) x += y; }
        if (lane == 31) wsum[wid] = x;
        __syncthreads();
        if (wid == 0) {
            int w = wsum[lane];
            #pragma unroll
            for (int d = 1; d < 32; d <<= 1) { int y = __shfl_up_sync(0xffffffffu, w, d); if (lane >= d) w += y; }
            wsum[lane] = w;
        }
        __syncthreads();
        int excl = carry + x - v + (wid ? wsum[wid - 1] : 0);
        if (i < NN) { g_off[b * NN + i] = excl; g_cur[b * NN + i] = excl; }
        __syncthreads();
        if (tid == 1023) carry = excl + v;
        __syncthreads();
    }
    // restore the all-zero invariant for the next call (all reads above are done)
    __syncthreads();
    for (int i = tid; i < NN; i += 1024) g_deg[b * NN + i] = 0;
}

__global__ void k_scatter(const int* __restrict__ eidx) {
    int b = blockIdx.y;
    long e = (long)blockIdx.x * 256 + threadIdx.x;
    if (e >= EE) return;
    int src = eidx[(size_t)b * 2 * EE + e];
    int dst = eidx[(size_t)b * 2 * EE + EE + e];
    int pos = atomicAdd(&g_cur[b * NN + dst], 1);
    g_sedge[(size_t)b * EE + pos] = make_int2(src, (int)e);
}

// ---------------- GEMM1 v2 (register-blocked): xl1 = x@Wl (z=0), xr1 = x@Wr (z=1) ----------------
__global__ void k_gemm1(const float* __restrict__ x,
                        const float* __restrict__ Wl, const float* __restrict__ Wr) {
    __shared__ float sW[FF * C1];    // 32KB
    __shared__ float sx[64][FF];     // 16KB
    const float* W = blockIdx.z ? Wr : Wl;
    float* out = blockIdx.z ? g_xr1 : g_xl1;
    int tid = threadIdx.x, b = blockIdx.y;
    for (int i = tid; i < FF * C1 / 4; i += 256)
        ((float4*)sW)[i] = ((const float4*)W)[i];
    int row0 = blockIdx.x * 64;
    #pragma unroll
    for (int j = 0; j < 4; j++) {
        int idx = tid + j * 256;
        int r4 = idx >> 4, kq = idx & 15;
        int row = row0 + r4;
        float4 v = make_float4(0.f, 0.f, 0.f, 0.f);
        if (row < NN) v = *(const float4*)&x[((size_t)b*NN + row)*FF + kq*4];
        ((float4*)&sx[r4][0])[kq] = v;
    }
    __syncthreads();
    int cp = tid & 31;
    int rg = tid >> 5;
    u64 acc[8][2];
    #pragma unroll
    for (int rr = 0; rr < 8; rr++) { acc[rr][0] = 0; acc[rr][1] = 0; }
    for (int k = 0; k < FF; k++) {
        float4 w = *(const float4*)&sW[k*C1 + cp*4];
        u64 w01 = F2PK(w.x, w.y), w23 = F2PK(w.z, w.w);
        #pragma unroll
        for (int rr = 0; rr < 8; rr++) {
            float xv = sx[rg*8 + rr][k];
            u64 xp = F2PK(xv, xv);
            acc[rr][0] = FMA2(xp, w01, acc[rr][0]);
            acc[rr][1] = FMA2(xp, w23, acc[rr][1]);
        }
    }
    #pragma unroll
    for (int rr = 0; rr < 8; rr++) {
        int row = row0 + rg*8 + rr;
        if (row < NN) {
            float2 p0 = F2UP(acc[rr][0]), p1 = F2UP(acc[rr][1]);
            *(float4*)&out[((size_t)b*NN + row)*C1 + cp*4] = make_float4(p0.x, p0.y, p1.x, p1.y);
        }
    }
}

// ---------------- conv1: warp-per-dst-node, 4-edge interleaved, packed f32x2 ----------------
// One LDS.128 of weights per k serves FOUR edges (16 crossbar phases/edge vs 32 before).
// avAB: attrs of edges i (lanes 0-15) / i+1 (lanes 16-31); avCD: edges i+2 / i+3.
// grid: (ceil(NN/8), BB), block 256.
__global__ void k_edge1g(const float* __restrict__ eattr,
                         const float* __restrict__ We, const float* __restrict__ att,
                         const float* __restrict__ b1) {
    __shared__ float sWe[ED * C1];  // 8KB
    __shared__ float satt[H1 * HID];
    int tid = threadIdx.x, b = blockIdx.y;
    for (int i = tid; i < ED * C1; i += 256) sWe[i] = We[i];
    if (tid < H1 * HID) satt[tid] = att[tid];
    __syncthreads();
    int warp = tid >> 5, lane = tid & 31;
    int n = blockIdx.x * 8 + warp;
    if (n >= NN) return;
    int nb = b * NN + n;
    int start = g_off[nb];
    int end = (n == NN - 1) ? EE : g_off[nb + 1];
    int c0 = lane * 4;
    const float4* xl1v = (const float4*)g_xl1;
    size_t rowq = ((size_t)b * NN) * (C1 / 4) + (size_t)lane;
    float4 xrf = ((const float4*)g_xr1)[(size_t)nb * (C1/4) + lane];
    u64 xr0 = F2PK(xrf.x, xrf.y), xr1 = F2PK(xrf.z, xrf.w);
    u64 acc0 = 0, acc1 = 0;
    float den = 0.f;
    int h = lane >> 2;
    int cl = (lane & 3) * 4;
    u64 attp0 = F2PK(satt[h*HID+cl+0], satt[h*HID+cl+1]);
    u64 attp1 = F2PK(satt[h*HID+cl+2], satt[h*HID+cl+3]);
    const int2* sedge = g_sedge + (size_t)b * EE;
    const float* eab = eattr + (size_t)b * EE * ED;
    int halfe = lane >> 4;
    int tl = lane & 15;

    float avAB = 0.f, avCD = 0.f;
    float4 z4 = make_float4(0.f, 0.f, 0.f, 0.f);
    float4 xlA = z4, xlB = z4, xlC = z4, xlD = z4;
    if (start < end) {
        int2 e0 = sedge[start];
        int2 e1 = (start + 1 < end) ? sedge[start + 1] : e0;
        int2 e2 = (start + 2 < end) ? sedge[start + 2] : e0;
        int2 e3 = (start + 3 < end) ? sedge[start + 3] : e2;
        avAB = eab[(size_t)(halfe ? e1.y : e0.y)*ED + tl];
        avCD = eab[(size_t)(halfe ? e3.y : e2.y)*ED + tl];
        xlA = xl1v[rowq + (size_t)e0.x * (C1/4)];
        if (start + 1 < end) xlB = xl1v[rowq + (size_t)e1.x * (C1/4)];
        if (start + 2 < end) xlC = xl1v[rowq + (size_t)e2.x * (C1/4)];
        if (start + 3 < end) xlD = xl1v[rowq + (size_t)e3.x * (C1/4)];
    }
    for (int i = start; i < end; i += 4) {
        // prefetch next 4 edges
        float avAB2 = 0.f, avCD2 = 0.f;
        float4 xlA2 = z4, xlB2 = z4, xlC2 = z4, xlD2 = z4;
        if (i + 4 < end) {
            int2 e0 = sedge[i + 4];
            int2 e1 = (i + 5 < end) ? sedge[i + 5] : e0;
            int2 e2 = (i + 6 < end) ? sedge[i + 6] : e0;
            int2 e3 = (i + 7 < end) ? sedge[i + 7] : e2;
            avAB2 = eab[(size_t)(halfe ? e1.y : e0.y)*ED + tl];
            avCD2 = eab[(size_t)(halfe ? e3.y : e2.y)*ED + tl];
            xlA2 = xl1v[rowq + (size_t)e0.x * (C1/4)];
            if (i + 5 < end) xlB2 = xl1v[rowq + (size_t)e1.x * (C1/4)];
            if (i + 6 < end) xlC2 = xl1v[rowq + (size_t)e2.x * (C1/4)];
            if (i + 7 < end) xlD2 = xl1v[rowq + (size_t)e3.x * (C1/4)];
        }
        bool vB = (i + 1 < end), vC = (i + 2 < end), vD = (i + 3 < end);

        u64 xlA0 = F2PK(xlA.x, xlA.y), xlA1 = F2PK(xlA.z, xlA.w);
        u64 xlB0 = F2PK(xlB.x, xlB.y), xlB1 = F2PK(xlB.z, xlB.w);
        u64 xlC0 = F2PK(xlC.x, xlC.y), xlC1 = F2PK(xlC.z, xlC.w);
        u64 xlD0 = F2PK(xlD.x, xlD.y), xlD1 = F2PK(xlD.z, xlD.w);
        u64 eeA0 = 0, eeA1 = 0, eeB0 = 0, eeB1 = 0;
        u64 eeC0 = 0, eeC1 = 0, eeD0 = 0, eeD1 = 0;
        #pragma unroll
        for (int k = 0; k < ED; k++) {
            float aA = __shfl_sync(0xffffffffu, avAB, k);
            float aB = __shfl_sync(0xffffffffu, avAB, 16 | k);
            float aC = __shfl_sync(0xffffffffu, avCD, k);
            float aD = __shfl_sync(0xffffffffu, avCD, 16 | k);
            float4 w = *(const float4*)&sWe[k*C1 + c0];   // ONE LDS serves 4 edges
            u64 w01 = F2PK(w.x, w.y), w23 = F2PK(w.z, w.w);
            u64 aAp = F2PK(aA, aA), aBp = F2PK(aB, aB);
            u64 aCp = F2PK(aC, aC), aDp = F2PK(aD, aD);
            eeA0 = FMA2(aAp, w01, eeA0); eeA1 = FMA2(aAp, w23, eeA1);
            eeB0 = FMA2(aBp, w01, eeB0); eeB1 = FMA2(aBp, w23, eeB1);
            eeC0 = FMA2(aCp, w01, eeC0); eeC1 = FMA2(aCp, w23, eeC1);
            eeD0 = FMA2(aDp, w01, eeD0); eeD1 = FMA2(aDp, w23, eeD1);
        }
        u64 gA0 = LRELU2(ADD2(xlA0, ADD2(xr0, eeA0)));
        u64 gA1 = LRELU2(ADD2(xlA1, ADD2(xr1, eeA1)));
        u64 gB0 = LRELU2(ADD2(xlB0, ADD2(xr0, eeB0)));
        u64 gB1 = LRELU2(ADD2(xlB1, ADD2(xr1, eeB1)));
        u64 gC0 = LRELU2(ADD2(xlC0, ADD2(xr0, eeC0)));
        u64 gC1 = LRELU2(ADD2(xlC1, ADD2(xr1, eeC1)));
        u64 gD0 = LRELU2(ADD2(xlD0, ADD2(xr0, eeD0)));
        u64 gD1 = LRELU2(ADD2(xlD1, ADD2(xr1, eeD1)));
        float2 sfA = F2UP(FMA2(gA1, attp1, MUL2(gA0, attp0)));
        float2 sfB = F2UP(FMA2(gB1, attp1, MUL2(gB0, attp0)));
        float2 sfC = F2UP(FMA2(gC1, attp1, MUL2(gC0, attp0)));
        float2 sfD = F2UP(FMA2(gD1, attp1, MUL2(gD0, attp0)));
        float sA = sfA.x + sfA.y, sB = sfB.x + sfB.y;
        float sC = sfC.x + sfC.y, sD = sfD.x + sfD.y;
        sA += __shfl_xor_sync(0xffffffffu, sA, 1);
        sB += __shfl_xor_sync(0xffffffffu, sB, 1);
        sC += __shfl_xor_sync(0xffffffffu, sC, 1);
        sD += __shfl_xor_sync(0xffffffffu, sD, 1);
        sA += __shfl_xor_sync(0xffffffffu, sA, 2);
        sB += __shfl_xor_sync(0xffffffffu, sB, 2);
        sC += __shfl_xor_sync(0xffffffffu, sC, 2);
        sD += __shfl_xor_sync(0xffffffffu, sD, 2);
        float exA = __expf(sA);
        float exB = vB ? __expf(sB) : 0.f;
        float exC = vC ? __expf(sC) : 0.f;
        float exD = vD ? __expf(sD) : 0.f;
        u64 exA2 = F2PK(exA, exA), exB2 = F2PK(exB, exB);
        u64 exC2 = F2PK(exC, exC), exD2 = F2PK(exD, exD);
        acc0 = FMA2(exA2, xlA0, acc0); acc1 = FMA2(exA2, xlA1, acc1);
        acc0 = FMA2(exB2, xlB0, acc0); acc1 = FMA2(exB2, xlB1, acc1);
        acc0 = FMA2(exC2, xlC0, acc0); acc1 = FMA2(exC2, xlC1, acc1);
        acc0 = FMA2(exD2, xlD0, acc0); acc1 = FMA2(exD2, xlD1, acc1);
        den += (exA + exB) + (exC + exD);
        avAB = avAB2; avCD = avCD2;
        xlA = xlA2; xlB = xlB2; xlC = xlC2; xlD = xlD2;
    }
    // epilogue: hx = elu(acc/den + bias)
    float inv = 1.f / (den + 1e-16f);
    float4 bv = ((const float4*)b1)[lane];
    float2 a01 = F2UP(acc0), a23 = F2UP(acc1);
    float o0 = a01.x * inv + bv.x;
    float o1 = a01.y * inv + bv.y;
    float o2 = a23.x * inv + bv.z;
    float o3 = a23.y * inv + bv.w;
    o0 = (o0 > 0.f) ? o0 : (__expf(o0) - 1.f);
    o1 = (o1 > 0.f) ? o1 : (__expf(o1) - 1.f);
    o2 = (o2 > 0.f) ? o2 : (__expf(o2) - 1.f);
    o3 = (o3 > 0.f) ? o3 : (__expf(o3) - 1.f);
    ((float4*)g_out1)[(size_t)nb * (C1/4) + lane] = make_float4(o0, o1, o2, o3);
}

// ---------------- GEMM2 v2 (register-blocked): 4 projections -> interleaved (conv2,skip) ----------------
__global__ void k_gemm2(const float* __restrict__ Wl2, const float* __restrict__ Wr2,
                        const float* __restrict__ Wls, const float* __restrict__ Wrs) {
    __shared__ float sW[C1 * 64];    // 32KB
    __shared__ float sh[32][C1];     // 16KB
    __shared__ float ss[32][C1];     // 16KB
    int tid = threadIdx.x, b = blockIdx.y;
    for (int i = tid; i < C1 * HID; i += 256) {
        int k = i >> 4, c = i & 15;
        sW[k*64 + c]      = Wl2[i];
        sW[k*64 + 16 + c] = Wr2[i];
        sW[k*64 + 32 + c] = Wls[i];
        sW[k*64 + 48 + c] = Wrs[i];
    }
    int row0 = blockIdx.x * 32;
    #pragma unroll
    for (int j = 0; j < 4; j++) {
        int idx = tid + j * 256;
        int r4 = idx >> 5, kq = idx & 31;
        int row = row0 + r4;
        float4 hv = make_float4(0.f, 0.f, 0.f, 0.f);
        float4 sk = hv;
        if (row < NN) {
            hv = *(const float4*)&g_out1[((size_t)b*NN + row)*C1 + kq*4];
            sk = *(const float4*)&g_xl1[((size_t)b*NN + row)*C1 + kq*4];
        }
        ((float4*)&sh[r4][0])[kq] = hv;
        ((float4*)&ss[r4][0])[kq] = make_float4(hv.x + sk.x, hv.y + sk.y, hv.z + sk.z, hv.w + sk.w);
    }
    __syncthreads();
    int cp = tid & 31;
    int rg = tid >> 5;
    int arr = cp >> 3;
    const float (*rows)[C1] = (cp < 16) ? sh : ss;
    u64 acc[4] = {0, 0, 0, 0};
    for (int k = 0; k < C1; k++) {
        u64 w = *(const u64*)&sW[k*64 + cp*2];
        #pragma unroll
        for (int rr = 0; rr < 4; rr++) {
            float xv = rows[rg*4 + rr][k];
            acc[rr] = FMA2(F2PK(xv, xv), w, acc[rr]);
        }
    }
    int c = (cp & 7) * 2;
    #pragma unroll
    for (int rr = 0; rr < 4; rr++) {
        int row = row0 + rg*4 + rr;
        if (row < NN) {
            size_t off2 = (((size_t)b*NN + row)*HID + c) * 2;
            float2 res = F2UP(acc[rr]);
            if (arr == 0)      { g_xlP[off2]     = res.x; g_xlP[off2 + 2] = res.y; }
            else if (arr == 1) { g_xrP[off2]     = res.x; g_xrP[off2 + 2] = res.y; }
            else if (arr == 2) { g_xlP[off2 + 1] = res.x; g_xlP[off2 + 3] = res.y; }
            else               { g_xrP[off2 + 1] = res.x; g_xrP[off2 + 3] = res.y; }
        }
    }
}

// ---------------- conv2+skip: warp-per-node, 2 edges/warp, packed (conv2,skip) lanes ----------------
// lanes 0-15: even edges, lanes 16-31: odd edges; lane channel t = lane&15 covers BOTH convs packed.
// Warp-uniform trip count; invalid edges contribute exp2 = 0. grid: (ceil(NN/8), BB), block 256
__global__ void k_edge2g(const float* __restrict__ eattr,
                         const float* __restrict__ We2, const float* __restrict__ att2,
                         const float* __restrict__ b2,
                         const float* __restrict__ WeS, const float* __restrict__ attS,
                         const float* __restrict__ bS,
                         const float* __restrict__ linW, const float* __restrict__ linb,
                         const float* __restrict__ lng, const float* __restrict__ lnb,
                         float* __restrict__ out) {
    __shared__ u64 sWeP[ED * HID];   // (We2, WeS) interleaved, 2KB
    __shared__ u64 sattP[HID];
    __shared__ float sLW[HID * HID];
    int tid = threadIdx.x, b = blockIdx.y;
    if (tid < ED*HID) { sWeP[tid] = F2PK(We2[tid], WeS[tid]); sLW[tid] = linW[tid]; }
    if (tid < HID)    sattP[tid] = F2PK(att2[tid], attS[tid]);
    __syncthreads();
    int warp = tid >> 5, lane = tid & 31;
    int n = blockIdx.x * 8 + warp;
    if (n >= NN) return;
    int nb = b * NN + n;
    int start = g_off[nb];
    int end = (n == NN - 1) ? EE : g_off[nb + 1];
    int t = lane & 15;
    int half = lane >> 4;      // 0: even edges, 1: odd edges
    const u64* xlP = (const u64*)g_xlP + (size_t)b * NN * HID;
    u64 xr = ((const u64*)g_xrP)[(size_t)nb * HID + t];
    u64 attp = sattP[t];
    u64 acc = 0, den = 0;
    const int2* sedge = g_sedge + (size_t)b * EE;
    const float* eab = eattr + (size_t)b * EE * ED;

    int cnt = end - start;
    int iters = (cnt + 1) >> 1;          // warp-uniform
    int i = start + half;                // this half's first edge
    bool valid = (i < end);
    float av = 0.f; u64 xl = 0;
    if (valid) {
        int2 e = sedge[i];
        av = eab[(size_t)e.y*ED + t];
        xl = xlP[(size_t)e.x * HID + t];
    }
    for (int it = 0; it < iters; it++) {
        int inext = i + 2;
        bool valid2 = (inext < end);
        float av2 = 0.f; u64 xl2 = 0;
        if (valid2) {
            int2 e = sedge[inext];
            av2 = eab[(size_t)e.y*ED + t];
            xl2 = xlP[(size_t)e.x * HID + t];
        }
        u64 ee = 0;
        #pragma unroll
        for (int k = 0; k < ED; k++) {
            float a = __shfl_sync(0xffffffffu, av, (lane & 16) | k);
            ee = FMA2(F2PK(a, a), sWeP[k*HID + t], ee);
        }
        u64 g = LRELU2(ADD2(xl, ADD2(xr, ee)));
        u64 sp = MUL2(g, attp);
        #pragma unroll
        for (int d = 1; d < 16; d <<= 1) sp = ADD2(sp, SHFLX64(sp, d));
        float2 sf = F2UP(sp);          // (s_conv2, s_skip) for this half's edge
        u64 exp2 = 0;                  // packed (0.0f, 0.0f)
        if (valid) exp2 = F2PK(__expf(sf.x), __expf(sf.y));
        acc = FMA2(exp2, xl, acc);
        den = ADD2(den, exp2);
        i = inext; av = av2; xl = xl2; valid = valid2;
    }
    // combine halves (even/odd edge streams) — all lanes converged here
    acc = ADD2(acc, SHFLX64(acc, 16));
    den = ADD2(den, SHFLX64(den, 16));
    // epilogue: normalize + bias, lin on skip, add, layernorm
    float2 a = F2UP(acc), d2 = F2UP(den);
    float x1 = a.x / (d2.x + 1e-16f) + b2[t];
    float xs = a.y / (d2.y + 1e-16f) + bS[t];
    float x2 = linb[t];
    #pragma unroll
    for (int j = 0; j < HID; j++) {
        float xj = __shfl_sync(0xffffffffu, xs, j);   // lane j holds xs[j] (both halves identical)
        x2 += xj * sLW[t*HID + j];
    }
    float y = x1 + x2;
    float mu = y;
    #pragma unroll
    for (int d = 1; d < 16; d <<= 1) mu += __shfl_xor_sync(0xffffffffu, mu, d);
    mu *= (1.f / 16.f);
    float dv = y - mu;
    float var = dv * dv;
    #pragma unroll
    for (int d = 1; d < 16; d <<= 1) var += __shfl_xor_sync(0xffffffffu, var, d);
    var *= (1.f / 16.f);
    if (lane < 16)
        out[(size_t)nb * HID + t] = dv * rsqrtf(var + 1e-5f) * lng[t] + lnb[t];
}

extern "C" void kernel_launch(void* const* d_in, const int* in_sizes, int n_in,
                              void* d_out, int out_size) {
    const float* x      = (const float*)d_in[0];
    const float* eattr  = (const float*)d_in[1];
    const int*   eidx   = (const int*)  d_in[2];
    const float* c1_Wl  = (const float*)d_in[3];
    const float* c1_Wr  = (const float*)d_in[4];
    const float* c1_We  = (const float*)d_in[5];
    const float* c1_att = (const float*)d_in[6];
    const float* c1_b   = (const float*)d_in[7];
    const float* c2_Wl  = (const float*)d_in[8];
    const float* c2_Wr  = (const float*)d_in[9];
    const float* c2_We  = (const float*)d_in[10];
    const float* c2_att = (const float*)d_in[11];
    const float* c2_b   = (const float*)d_in[12];
    const float* s_Wl   = (const float*)d_in[13];
    const float* s_Wr   = (const float*)d_in[14];
    const float* s_We   = (const float*)d_in[15];
    const float* s_att  = (const float*)d_in[16];
    const float* s_b    = (const float*)d_in[17];
    const float* lin_W  = (const float*)d_in[18];
    const float* lin_b  = (const float*)d_in[19];
    const float* ln_g   = (const float*)d_in[20];
    const float* ln_b   = (const float*)d_in[21];

    // g_deg is all-zero here (module-load init on first call; k_scan restores it)
    k_count<<<dim3((EE + 255) / 256, BB), 256>>>(eidx);
    k_scan<<<BB, 1024>>>();
    k_scatter<<<dim3((EE + 255) / 256, BB), 256>>>(eidx);
    k_gemm1<<<dim3((NN + 63) / 64, BB, 2), 256>>>(x, c1_Wl, c1_Wr);   // 4th launch -> profiled control
    k_edge1g<<<dim3((NN + 7) / 8, BB), 256>>>(eattr, c1_We, c1_att, c1_b);
    k_gemm2<<<dim3((NN + 31) / 32, BB), 256>>>(c2_Wl, c2_Wr, s_Wl, s_Wr);
    k_edge2g<<<dim3((NN + 7) / 8, BB), 256>>>(eattr, c2_We, c2_att, c2_b,
                                              s_We, s_att, s_b,
                                              lin_W, lin_b, ln_g, ln_b, (float*)d_out);
}